// round 8
// baseline (speedup 1.0000x reference)
#include <cuda_runtime.h>

#define NN 50000
#define DD 128
#define EMAX 800000

// Scratch (device globals: no allocation allowed)
__device__ float g_mean[NN * DD];
__device__ float g_h[NN * DD];
__device__ float g_wt[2][256 * 128];   // [layer][k2][2*j+h] = W^T[2*k2+h][j]
__device__ int   g_deg[NN];
__device__ int   g_cur[NN];
__device__ int   g_rowptr[NN + 1];
__device__ int   g_esrc[EMAX];
__device__ int   g_idx64;

// ---------------------------------------------------------------------------
// Detect whether edge_index is int64 (hi words all zero) or int32.
// ---------------------------------------------------------------------------
__global__ void detect_kernel(const unsigned int* __restrict__ ei) {
    __shared__ int any_nonzero;
    if (threadIdx.x == 0) any_nonzero = 0;
    __syncthreads();
    if (ei[2 * threadIdx.x + 1] != 0u) atomicOr(&any_nonzero, 1);
    __syncthreads();
    if (threadIdx.x == 0) g_idx64 = (any_nonzero == 0) ? 1 : 0;
}

// ---------------------------------------------------------------------------
// Pre-transpose weights into g_wt with k-pair interleave:
//   g_wt[layer][k2*256 + 2*j + (k&1)] = W[j][k],  k = krow in 0..255
// grid (128, 4), 128 thr. y: 0=W1l,1=W1r,2=W2l,3=W2r.
// ---------------------------------------------------------------------------
__global__ void transpose_kernel(const float* __restrict__ W1l,
                                 const float* __restrict__ W1r,
                                 const float* __restrict__ W2l,
                                 const float* __restrict__ W2r) {
    int k = blockIdx.x, y = blockIdx.y, j = threadIdx.x;
    const float* W = (y == 0) ? W1l : (y == 1) ? W1r : (y == 2) ? W2l : W2r;
    int krow = k + (y & 1) * 128;
    int k2 = krow >> 1, h = krow & 1;
    g_wt[y >> 1][k2 * 256 + 2 * j + h] = W[j * 128 + k];
}

// ---------------------------------------------------------------------------
// CSR build
// ---------------------------------------------------------------------------
__global__ void zero_small_kernel() {
    int i = blockIdx.x * blockDim.x + threadIdx.x;
    if (i < NN) { g_deg[i] = 0; g_cur[i] = 0; }
}

__device__ __forceinline__ int load_dst(const void* ei, unsigned e, unsigned E) {
    if (g_idx64) return (int)((const long long*)ei)[e + E];
    return ((const int*)ei)[e + E];
}
__device__ __forceinline__ int load_src(const void* ei, unsigned e, unsigned E) {
    if (g_idx64) return (int)((const long long*)ei)[e];
    return ((const int*)ei)[e];
}

__global__ void hist_kernel(const void* __restrict__ ei, int E) {
    unsigned e = blockIdx.x * blockDim.x + threadIdx.x;
    if (e >= (unsigned)E) return;
    atomicAdd(&g_deg[load_dst(ei, e, E)], 1);
}

__global__ void scan_kernel() {
    __shared__ int sp[1024];
    int t = threadIdx.x;
    const int CH = (NN + 1023) / 1024;  // 49
    int base = t * CH;
    int s = 0;
    for (int i = 0; i < CH; i++) {
        int idx = base + i;
        if (idx < NN) s += g_deg[idx];
    }
    sp[t] = s;
    __syncthreads();
    for (int off = 1; off < 1024; off <<= 1) {
        int v = (t >= off) ? sp[t - off] : 0;
        __syncthreads();
        sp[t] += v;
        __syncthreads();
    }
    int run = (t == 0) ? 0 : sp[t - 1];
    for (int i = 0; i < CH; i++) {
        int idx = base + i;
        if (idx < NN) { g_rowptr[idx] = run; run += g_deg[idx]; }
    }
    if (t == 1023) g_rowptr[NN] = run;
}

__global__ void scatter_kernel(const void* __restrict__ ei, int E) {
    unsigned e = blockIdx.x * blockDim.x + threadIdx.x;
    if (e >= (unsigned)E) return;
    int src = load_src(ei, e, E);
    int dst = load_dst(ei, e, E);
    int pos = g_rowptr[dst] + atomicAdd(&g_cur[dst], 1);
    g_esrc[pos] = src;
}

// ---------------------------------------------------------------------------
// Aggregation: one warp per destination node (mean fused, plain stores).
// ---------------------------------------------------------------------------
__global__ void __launch_bounds__(256)
agg_kernel(const float* __restrict__ xin) {
    int warp = (blockIdx.x * blockDim.x + threadIdx.x) >> 5;
    int lane = threadIdx.x & 31;
    if (warp >= NN) return;

    int start = g_rowptr[warp];
    int end   = g_rowptr[warp + 1];

    float4 acc = make_float4(0.f, 0.f, 0.f, 0.f);
    int j = start;
    for (; j + 4 <= end; j += 4) {
        int s0 = g_esrc[j + 0], s1 = g_esrc[j + 1];
        int s2 = g_esrc[j + 2], s3 = g_esrc[j + 3];
        float4 v0 = __ldg(((const float4*)(xin + (size_t)s0 * DD)) + lane);
        float4 v1 = __ldg(((const float4*)(xin + (size_t)s1 * DD)) + lane);
        float4 v2 = __ldg(((const float4*)(xin + (size_t)s2 * DD)) + lane);
        float4 v3 = __ldg(((const float4*)(xin + (size_t)s3 * DD)) + lane);
        acc.x += v0.x + v1.x + v2.x + v3.x;
        acc.y += v0.y + v1.y + v2.y + v3.y;
        acc.z += v0.z + v1.z + v2.z + v3.z;
        acc.w += v0.w + v1.w + v2.w + v3.w;
    }
    for (; j < end; j++) {
        int s = g_esrc[j];
        float4 v = __ldg(((const float4*)(xin + (size_t)s * DD)) + lane);
        acc.x += v.x; acc.y += v.y; acc.z += v.z; acc.w += v.w;
    }

    float inv = 1.0f / fmaxf((float)(end - start), 1.0f);
    acc.x *= inv; acc.y *= inv; acc.z *= inv; acc.w *= inv;
    ((float4*)(g_mean + (size_t)warp * DD))[lane] = acc;
}

// ---------------------------------------------------------------------------
// JAX threefry2x32-20, key=(0,42), partitionable, float64 uniform.
// ---------------------------------------------------------------------------
__device__ __forceinline__ unsigned rotl32(unsigned x, int r) {
    return (x << r) | (x >> (32 - r));
}

__device__ __forceinline__ float drop_mask(unsigned f) {
    const unsigned k0 = 0u, k1 = 42u;
    const unsigned k2 = k0 ^ k1 ^ 0x1BD11BDAu;
    unsigned x0 = 0u + k0;
    unsigned x1 = f + k1;

#define TF_ROUND(r) do { x0 += x1; x1 = rotl32(x1, (r)); x1 ^= x0; } while (0)
#define TF_BLOCK_A  do { TF_ROUND(13); TF_ROUND(15); TF_ROUND(26); TF_ROUND(6);  } while (0)
#define TF_BLOCK_B  do { TF_ROUND(17); TF_ROUND(29); TF_ROUND(16); TF_ROUND(24); } while (0)

    TF_BLOCK_A; x0 += k1; x1 += k2 + 1u;
    TF_BLOCK_B; x0 += k2; x1 += k0 + 2u;
    TF_BLOCK_A; x0 += k0; x1 += k1 + 3u;
    TF_BLOCK_B; x0 += k1; x1 += k2 + 4u;
    TF_BLOCK_A; x0 += k2; x1 += k0 + 5u;

#undef TF_ROUND
#undef TF_BLOCK_A
#undef TF_BLOCK_B

    unsigned long long b =
        ((unsigned long long)x0 << 32) | (unsigned long long)x1;
    b = (b >> 12) | 0x3FF0000000000000ULL;
    double u = __longlong_as_double((long long)b) - 1.0;
    return (u < 0.8) ? 1.25f : 0.0f;
}

// ---------------------------------------------------------------------------
// Node update with packed dual-fp32 FMA (fma.rn.f32x2):
//   out = [mean | x] @ [Wl;Wr]^T + b  (K = 256)
// Accumulators hold (even-k, odd-k) partial sums, folded in epilogue.
// ---------------------------------------------------------------------------
__device__ __forceinline__ void ffma2(unsigned long long& d,
                                      unsigned long long a,
                                      unsigned long long b) {
    asm("fma.rn.f32x2 %0, %1, %2, %0;" : "+l"(d) : "l"(a), "l"(b));
}

__device__ __forceinline__ float fold2(unsigned long long v) {
    float lo = __uint_as_float((unsigned)(v & 0xffffffffULL));
    float hi = __uint_as_float((unsigned)(v >> 32));
    return lo + hi;
}

template <bool DROP>
__global__ void __launch_bounds__(256, 1)
node_kernel(const float* __restrict__ xin,
            const float* __restrict__ wt,     // [128 k2][256] pair-interleaved
            const float* __restrict__ bias,
            float* __restrict__ out) {
    extern __shared__ float ss[];  // [64][256] : cols 0..127 mean, 128..255 x

    int t = threadIdx.x;
    int row0 = blockIdx.x * 64;

    for (int i = t; i < 4096; i += 256) {   // 64 rows * 64 float4
        int r = i >> 6, c4 = i & 63;
        int row = row0 + r;
        float4 v = make_float4(0.f, 0.f, 0.f, 0.f);
        if (row < NN) {
            if (c4 < 32)
                v = __ldg(((const float4*)(g_mean + (size_t)row * DD)) + c4);
            else
                v = __ldg(((const float4*)(xin + (size_t)row * DD)) + (c4 - 32));
        }
        ((float4*)ss)[i] = v;
    }
    __syncthreads();

    int jq = t & 31;   // output col quad: cols 4*jq..4*jq+3
    int rg = t >> 5;   // rows rg + 8*rr

    unsigned long long acc[8][4];
#pragma unroll
    for (int rr = 0; rr < 8; rr++)
#pragma unroll
        for (int c = 0; c < 4; c++) acc[rr][c] = 0ULL;

#pragma unroll 2
    for (int k4 = 0; k4 < 64; k4++) {
        // weights for k-pairs k2a=2*k4, k2b=2*k4+1; 8 floats per k2 for 4 j's
        const unsigned long long* wa =
            (const unsigned long long*)(wt + (2 * k4) * 256 + 8 * jq);
        const unsigned long long* wb =
            (const unsigned long long*)(wt + (2 * k4 + 1) * 256 + 8 * jq);
        ulonglong2 wa0 = __ldg((const ulonglong2*)wa);        // j0, j0+1 @ k2a
        ulonglong2 wa1 = __ldg((const ulonglong2*)(wa + 2));  // j0+2, j0+3 @ k2a
        ulonglong2 wb0 = __ldg((const ulonglong2*)wb);
        ulonglong2 wb1 = __ldg((const ulonglong2*)(wb + 2));
#pragma unroll
        for (int rr = 0; rr < 8; rr++) {
            int r = rg + rr * 8;
            ulonglong2 sv = ((const ulonglong2*)(ss + r * 256))[k4];
            // sv.x = (s[4k4], s[4k4+1]) = k2a pair ; sv.y = k2b pair
            ffma2(acc[rr][0], wa0.x, sv.x);
            ffma2(acc[rr][1], wa0.y, sv.x);
            ffma2(acc[rr][2], wa1.x, sv.x);
            ffma2(acc[rr][3], wa1.y, sv.x);
            ffma2(acc[rr][0], wb0.x, sv.y);
            ffma2(acc[rr][1], wb0.y, sv.y);
            ffma2(acc[rr][2], wb1.x, sv.y);
            ffma2(acc[rr][3], wb1.y, sv.y);
        }
    }

    float4 bv = __ldg(((const float4*)bias) + jq);
#pragma unroll
    for (int rr = 0; rr < 8; rr++) {
        int row = row0 + rg + rr * 8;
        if (row >= NN) continue;
        float4 o;
        o.x = fold2(acc[rr][0]) + bv.x;
        o.y = fold2(acc[rr][1]) + bv.y;
        o.z = fold2(acc[rr][2]) + bv.z;
        o.w = fold2(acc[rr][3]) + bv.w;
        if (DROP) {
            unsigned base = (unsigned)row * DD + 4 * jq;
            o.x = fmaxf(o.x, 0.f) * drop_mask(base + 0);
            o.y = fmaxf(o.y, 0.f) * drop_mask(base + 1);
            o.z = fmaxf(o.z, 0.f) * drop_mask(base + 2);
            o.w = fmaxf(o.w, 0.f) * drop_mask(base + 3);
        }
        *(float4*)(out + (size_t)row * DD + 4 * jq) = o;
    }
}

// ---------------------------------------------------------------------------
extern "C" void kernel_launch(void* const* d_in, const int* in_sizes, int n_in,
                              void* d_out, int out_size) {
    const float* x   = (const float*)d_in[0];
    const void*  ei  = d_in[1];
    const float* W1l = (const float*)d_in[2];
    const float* W1r = (const float*)d_in[3];
    const float* b1  = (const float*)d_in[4];
    const float* W2l = (const float*)d_in[5];
    const float* W2r = (const float*)d_in[6];
    const float* b2  = (const float*)d_in[7];
    float* out = (float*)d_out;

    int E = in_sizes[1] / 2;

    const int SMEM = 64 * 256 * (int)sizeof(float);  // 65536
    cudaFuncSetAttribute(node_kernel<true>,
                         cudaFuncAttributeMaxDynamicSharedMemorySize, SMEM);
    cudaFuncSetAttribute(node_kernel<false>,
                         cudaFuncAttributeMaxDynamicSharedMemorySize, SMEM);

    float* h_ptr  = nullptr;
    float* wt_ptr = nullptr;
    cudaGetSymbolAddress((void**)&h_ptr, g_h);
    cudaGetSymbolAddress((void**)&wt_ptr, g_wt);
    const float* wt1 = wt_ptr;
    const float* wt2 = wt_ptr + 256 * 128;

    int edge_blocks = (E + 255) / 256;
    int agg_blocks  = (NN * 32 + 255) / 256;
    int node_blocks = (NN + 63) / 64;

    // ----- One-time per launch: CSR build + weight transpose -----
    detect_kernel<<<1, 256>>>((const unsigned int*)ei);
    transpose_kernel<<<dim3(128, 4), 128>>>(W1l, W1r, W2l, W2r);
    zero_small_kernel<<<(NN + 255) / 256, 256>>>();
    hist_kernel<<<edge_blocks, 256>>>(ei, E);
    scan_kernel<<<1, 1024>>>();
    scatter_kernel<<<edge_blocks, 256>>>(ei, E);

    // ----- Layer 1 -----
    agg_kernel<<<agg_blocks, 256>>>(x);
    node_kernel<true><<<node_blocks, 256, SMEM>>>(x, wt1, b1, h_ptr);

    // ----- Layer 2 -----
    agg_kernel<<<agg_blocks, 256>>>(h_ptr);
    node_kernel<false><<<node_blocks, 256, SMEM>>>(h_ptr, wt2, b2, out);
}

// round 10
// speedup vs baseline: 1.8140x; 1.8140x over previous
#include <cuda_runtime.h>
#include <cstdint>

#define NN 50000
#define DD 128
#define EMAX 800000

// Scratch (device globals: no allocation allowed)
__device__ float    g_mean[NN * DD];
__device__ float    g_h[NN * DD];
// Fragment-packed tf32 weights: [layer][h][s(32)][t(16)][lane(32)][q(2)] u32
__device__ uint32_t g_btf[2 * 2 * 32 * 16 * 64];
__device__ int      g_deg[NN];
__device__ int      g_cur[NN];
__device__ int      g_rowptr[NN + 1];
__device__ int      g_esrc[EMAX];
__device__ int      g_idx64;

// ---------------------------------------------------------------------------
// Detect whether edge_index is int64 (hi words all zero) or int32.
// ---------------------------------------------------------------------------
__global__ void detect_kernel(const unsigned int* __restrict__ ei) {
    __shared__ int any_nonzero;
    if (threadIdx.x == 0) any_nonzero = 0;
    __syncthreads();
    if (ei[2 * threadIdx.x + 1] != 0u) atomicOr(&any_nonzero, 1);
    __syncthreads();
    if (threadIdx.x == 0) g_idx64 = (any_nonzero == 0) ? 1 : 0;
}

// ---------------------------------------------------------------------------
// Weight pack: tf32 hi/lo split in mma.m16n8k8 B-fragment order.
//   B col-major k8 x n8:  q=0 -> k = 8s + (l&3),  q=1 -> k += 4 ;  n = 8t + (l>>2)
//   value = Wcat^T[k][n] = (k<128 ? Wl[n][k] : Wr[n][k-128])
// 131072 elements total; 512 blocks x 256 threads.
// ---------------------------------------------------------------------------
__device__ __forceinline__ uint32_t cvt_tf32(float v) {
    uint32_t r;
    asm("cvt.rna.tf32.f32 %0, %1;" : "=r"(r) : "f"(v));
    return r;
}

__global__ void pack_kernel(const float* __restrict__ W1l,
                            const float* __restrict__ W1r,
                            const float* __restrict__ W2l,
                            const float* __restrict__ W2r) {
    int idx = blockIdx.x * blockDim.x + threadIdx.x;   // 0 .. 131071
    int e     = idx & 63;          // lane*2 + q
    int q     = e & 1;
    int l     = e >> 1;
    int t     = (idx >> 6) & 15;
    int s     = (idx >> 10) & 31;
    int h     = (idx >> 15) & 1;
    int layer = idx >> 16;

    int k = 8 * s + (l & 3) + 4 * q;
    int n = 8 * t + (l >> 2);

    const float* Wl = layer ? W2l : W1l;
    const float* Wr = layer ? W2r : W1r;
    float w = (k < 128) ? Wl[n * 128 + k] : Wr[n * 128 + (k - 128)];

    uint32_t hi = cvt_tf32(w);
    float    lo = w - __uint_as_float(hi);
    g_btf[idx] = h ? cvt_tf32(lo) : hi;
}

// ---------------------------------------------------------------------------
// CSR build
// ---------------------------------------------------------------------------
__global__ void zero_small_kernel() {
    int i = blockIdx.x * blockDim.x + threadIdx.x;
    if (i < NN) { g_deg[i] = 0; g_cur[i] = 0; }
}

__device__ __forceinline__ int load_dst(const void* ei, unsigned e, unsigned E) {
    if (g_idx64) return (int)((const long long*)ei)[e + E];
    return ((const int*)ei)[e + E];
}
__device__ __forceinline__ int load_src(const void* ei, unsigned e, unsigned E) {
    if (g_idx64) return (int)((const long long*)ei)[e];
    return ((const int*)ei)[e];
}

__global__ void hist_kernel(const void* __restrict__ ei, int E) {
    unsigned e = blockIdx.x * blockDim.x + threadIdx.x;
    if (e >= (unsigned)E) return;
    atomicAdd(&g_deg[load_dst(ei, e, E)], 1);
}

__global__ void scan_kernel() {
    __shared__ int sp[1024];
    int t = threadIdx.x;
    const int CH = (NN + 1023) / 1024;  // 49
    int base = t * CH;
    int s = 0;
    for (int i = 0; i < CH; i++) {
        int idx = base + i;
        if (idx < NN) s += g_deg[idx];
    }
    sp[t] = s;
    __syncthreads();
    for (int off = 1; off < 1024; off <<= 1) {
        int v = (t >= off) ? sp[t - off] : 0;
        __syncthreads();
        sp[t] += v;
        __syncthreads();
    }
    int run = (t == 0) ? 0 : sp[t - 1];
    for (int i = 0; i < CH; i++) {
        int idx = base + i;
        if (idx < NN) { g_rowptr[idx] = run; run += g_deg[idx]; }
    }
    if (t == 1023) g_rowptr[NN] = run;
}

__global__ void scatter_kernel(const void* __restrict__ ei, int E) {
    unsigned e = blockIdx.x * blockDim.x + threadIdx.x;
    if (e >= (unsigned)E) return;
    int src = load_src(ei, e, E);
    int dst = load_dst(ei, e, E);
    int pos = g_rowptr[dst] + atomicAdd(&g_cur[dst], 1);
    g_esrc[pos] = src;
}

// ---------------------------------------------------------------------------
// Aggregation: one warp per destination node (mean fused, plain stores).
// ---------------------------------------------------------------------------
__global__ void __launch_bounds__(256)
agg_kernel(const float* __restrict__ xin) {
    int warp = (blockIdx.x * blockDim.x + threadIdx.x) >> 5;
    int lane = threadIdx.x & 31;
    if (warp >= NN) return;

    int start = g_rowptr[warp];
    int end   = g_rowptr[warp + 1];

    float4 acc = make_float4(0.f, 0.f, 0.f, 0.f);
    int j = start;
    for (; j + 4 <= end; j += 4) {
        int s0 = g_esrc[j + 0], s1 = g_esrc[j + 1];
        int s2 = g_esrc[j + 2], s3 = g_esrc[j + 3];
        float4 v0 = __ldg(((const float4*)(xin + (size_t)s0 * DD)) + lane);
        float4 v1 = __ldg(((const float4*)(xin + (size_t)s1 * DD)) + lane);
        float4 v2 = __ldg(((const float4*)(xin + (size_t)s2 * DD)) + lane);
        float4 v3 = __ldg(((const float4*)(xin + (size_t)s3 * DD)) + lane);
        acc.x += v0.x + v1.x + v2.x + v3.x;
        acc.y += v0.y + v1.y + v2.y + v3.y;
        acc.z += v0.z + v1.z + v2.z + v3.z;
        acc.w += v0.w + v1.w + v2.w + v3.w;
    }
    for (; j < end; j++) {
        int s = g_esrc[j];
        float4 v = __ldg(((const float4*)(xin + (size_t)s * DD)) + lane);
        acc.x += v.x; acc.y += v.y; acc.z += v.z; acc.w += v.w;
    }

    float inv = 1.0f / fmaxf((float)(end - start), 1.0f);
    acc.x *= inv; acc.y *= inv; acc.z *= inv; acc.w *= inv;
    ((float4*)(g_mean + (size_t)warp * DD))[lane] = acc;
}

// ---------------------------------------------------------------------------
// JAX threefry2x32-20, key=(0,42), partitionable, float64 uniform.
// ---------------------------------------------------------------------------
__device__ __forceinline__ unsigned rotl32(unsigned x, int r) {
    return (x << r) | (x >> (32 - r));
}

__device__ __forceinline__ float drop_mask(unsigned f) {
    const unsigned k0 = 0u, k1 = 42u;
    const unsigned k2 = k0 ^ k1 ^ 0x1BD11BDAu;
    unsigned x0 = 0u + k0;
    unsigned x1 = f + k1;

#define TF_ROUND(r) do { x0 += x1; x1 = rotl32(x1, (r)); x1 ^= x0; } while (0)
#define TF_BLOCK_A  do { TF_ROUND(13); TF_ROUND(15); TF_ROUND(26); TF_ROUND(6);  } while (0)
#define TF_BLOCK_B  do { TF_ROUND(17); TF_ROUND(29); TF_ROUND(16); TF_ROUND(24); } while (0)

    TF_BLOCK_A; x0 += k1; x1 += k2 + 1u;
    TF_BLOCK_B; x0 += k2; x1 += k0 + 2u;
    TF_BLOCK_A; x0 += k0; x1 += k1 + 3u;
    TF_BLOCK_B; x0 += k1; x1 += k2 + 4u;
    TF_BLOCK_A; x0 += k2; x1 += k0 + 5u;

#undef TF_ROUND
#undef TF_BLOCK_A
#undef TF_BLOCK_B

    unsigned long long b =
        ((unsigned long long)x0 << 32) | (unsigned long long)x1;
    b = (b >> 12) | 0x3FF0000000000000ULL;
    double u = __longlong_as_double((long long)b) - 1.0;
    return (u < 0.8) ? 1.25f : 0.0f;
}

// ---------------------------------------------------------------------------
// Node update via mma.sync m16n8k8 tf32, 3xTF32 split:
//   out = [mean | x] @ Wcat^T + b ;  M=128/CTA, N=128, K=256 (2 chunks of 128)
// 8 warps = 4(M) x 2(N); warp tile 32x64 = 2 Mtiles x 8 Ntiles.
// ---------------------------------------------------------------------------
#define AS_STRIDE 132
#define BS_WORDS  32768                       // 2(h) * 16(s') * 16(t) * 64
#define SM_BS     0                           // 131072 B
#define SM_AS     (BS_WORDS * 4)              // 128*132*4 = 67584 B
#define SM_BIAS   (SM_AS + 128 * AS_STRIDE * 4)
#define SM_TOTAL  (SM_BIAS + 512)

__device__ __forceinline__ void mma_tf32(float* c, const uint32_t* a,
                                         uint32_t b0, uint32_t b1) {
    asm volatile(
        "mma.sync.aligned.m16n8k8.row.col.f32.tf32.tf32.f32 "
        "{%0,%1,%2,%3}, {%4,%5,%6,%7}, {%8,%9}, {%0,%1,%2,%3};"
        : "+f"(c[0]), "+f"(c[1]), "+f"(c[2]), "+f"(c[3])
        : "r"(a[0]), "r"(a[1]), "r"(a[2]), "r"(a[3]), "r"(b0), "r"(b1));
}

template <bool DROP>
__global__ void __launch_bounds__(256, 1)
node_kernel(const float* __restrict__ xin,
            const uint32_t* __restrict__ btf,   // this layer's packed weights
            const float* __restrict__ bias,
            float* __restrict__ out) {
    extern __shared__ char smem[];
    uint32_t* Bs = (uint32_t*)(smem + SM_BS);
    float*    As = (float*)(smem + SM_AS);
    float*    bs = (float*)(smem + SM_BIAS);

    int t    = threadIdx.x;
    int l    = t & 31;
    int warp = t >> 5;
    int mw   = warp >> 1;        // 0..3
    int nw   = warp & 1;         // 0..1
    int row0 = blockIdx.x * 128;

    if (t < 128) bs[t] = __ldg(bias + t);

    float acc[2][8][4];
#pragma unroll
    for (int i = 0; i < 2; i++)
#pragma unroll
        for (int tt = 0; tt < 8; tt++)
#pragma unroll
            for (int c = 0; c < 4; c++) acc[i][tt][c] = 0.f;

    for (int chunk = 0; chunk < 2; chunk++) {
        if (chunk) __syncthreads();

        // Stage A chunk: 128 rows x 128 cols fp32 (mean for chunk0, x for 1)
        const float* src = chunk ? xin : g_mean;
        for (int i = t; i < 128 * 32; i += 256) {
            int r  = i >> 5, c4 = i & 31;
            int row = row0 + r;
            float4 v = make_float4(0.f, 0.f, 0.f, 0.f);
            if (row < NN)
                v = __ldg(((const float4*)(src + (size_t)row * DD)) + c4);
            *(float4*)(As + r * AS_STRIDE + 4 * c4) = v;
        }

        // Stage B chunk: hi (16384 u32) + lo (16384 u32), linear copy
        for (int i = t; i < BS_WORDS; i += 256) {
            int h = i >> 14;
            Bs[i] = __ldg(btf + h * 32768 + chunk * 16384 + (i & 16383));
        }
        __syncthreads();

        // Compute: 16 k-steps of k8
#pragma unroll 4
        for (int s = 0; s < 16; s++) {
            // A fragments for 2 Mtiles, hi + lo
            uint32_t ah[2][4], al[2][4];
#pragma unroll
            for (int i = 0; i < 2; i++) {
                const float* Ar =
                    As + (mw * 32 + i * 16 + (l >> 2)) * AS_STRIDE +
                    8 * s + (l & 3);
                float a0 = Ar[0];
                float a1 = Ar[8 * AS_STRIDE];
                float a2 = Ar[4];
                float a3 = Ar[8 * AS_STRIDE + 4];
                ah[i][0] = cvt_tf32(a0);
                ah[i][1] = cvt_tf32(a1);
                ah[i][2] = cvt_tf32(a2);
                ah[i][3] = cvt_tf32(a3);
                al[i][0] = cvt_tf32(a0 - __uint_as_float(ah[i][0]));
                al[i][1] = cvt_tf32(a1 - __uint_as_float(ah[i][1]));
                al[i][2] = cvt_tf32(a2 - __uint_as_float(ah[i][2]));
                al[i][3] = cvt_tf32(a3 - __uint_as_float(ah[i][3]));
            }
#pragma unroll
            for (int tt = 0; tt < 8; tt++) {
                const uint32_t* Bp =
                    Bs + ((s * 16) + (nw * 8 + tt)) * 64 + l * 2;
                uint32_t bh0 = Bp[0],         bh1 = Bp[1];
                uint32_t bl0 = Bp[16384],     bl1 = Bp[16385];
#pragma unroll
                for (int i = 0; i < 2; i++) {
                    mma_tf32(acc[i][tt], ah[i], bh0, bh1);
                    mma_tf32(acc[i][tt], al[i], bh0, bh1);
                    mma_tf32(acc[i][tt], ah[i], bl0, bl1);
                }
            }
        }
    }

    // Epilogue: c0,c1 -> (row_a, col..col+1); c2,c3 -> (row_a+8, ...)
#pragma unroll
    for (int i = 0; i < 2; i++) {
#pragma unroll
        for (int tt = 0; tt < 8; tt++) {
            int row_a = row0 + mw * 32 + i * 16 + (l >> 2);
            int row_b = row_a + 8;
            int col   = nw * 64 + tt * 8 + 2 * (l & 3);
            float b0 = bs[col], b1 = bs[col + 1];

            if (row_a < NN) {
                float o0 = acc[i][tt][0] + b0;
                float o1 = acc[i][tt][1] + b1;
                if (DROP) {
                    unsigned f = (unsigned)row_a * DD + col;
                    o0 = fmaxf(o0, 0.f) * drop_mask(f);
                    o1 = fmaxf(o1, 0.f) * drop_mask(f + 1);
                }
                *(float2*)(out + (size_t)row_a * DD + col) = make_float2(o0, o1);
            }
            if (row_b < NN) {
                float o0 = acc[i][tt][2] + b0;
                float o1 = acc[i][tt][3] + b1;
                if (DROP) {
                    unsigned f = (unsigned)row_b * DD + col;
                    o0 = fmaxf(o0, 0.f) * drop_mask(f);
                    o1 = fmaxf(o1, 0.f) * drop_mask(f + 1);
                }
                *(float2*)(out + (size_t)row_b * DD + col) = make_float2(o0, o1);
            }
        }
    }
}

// ---------------------------------------------------------------------------
extern "C" void kernel_launch(void* const* d_in, const int* in_sizes, int n_in,
                              void* d_out, int out_size) {
    const float* x   = (const float*)d_in[0];
    const void*  ei  = d_in[1];
    const float* W1l = (const float*)d_in[2];
    const float* W1r = (const float*)d_in[3];
    const float* b1  = (const float*)d_in[4];
    const float* W2l = (const float*)d_in[5];
    const float* W2r = (const float*)d_in[6];
    const float* b2  = (const float*)d_in[7];
    float* out = (float*)d_out;

    int E = in_sizes[1] / 2;

    cudaFuncSetAttribute(node_kernel<true>,
                         cudaFuncAttributeMaxDynamicSharedMemorySize, SM_TOTAL);
    cudaFuncSetAttribute(node_kernel<false>,
                         cudaFuncAttributeMaxDynamicSharedMemorySize, SM_TOTAL);

    float* h_ptr = nullptr;
    uint32_t* btf_ptr = nullptr;
    cudaGetSymbolAddress((void**)&h_ptr, g_h);
    cudaGetSymbolAddress((void**)&btf_ptr, g_btf);
    const uint32_t* btf1 = btf_ptr;
    const uint32_t* btf2 = btf_ptr + 65536;

    int edge_blocks = (E + 255) / 256;
    int agg_blocks  = (NN * 32 + 255) / 256;
    int node_blocks = (NN + 127) / 128;   // 391

    // ----- One-time per launch: CSR build + weight pack -----
    detect_kernel<<<1, 256>>>((const unsigned int*)ei);
    pack_kernel<<<512, 256>>>(W1l, W1r, W2l, W2r);
    zero_small_kernel<<<(NN + 255) / 256, 256>>>();
    hist_kernel<<<edge_blocks, 256>>>(ei, E);
    scan_kernel<<<1, 1024>>>();
    scatter_kernel<<<edge_blocks, 256>>>(ei, E);

    // ----- Layer 1 -----
    agg_kernel<<<agg_blocks, 256>>>(x);
    node_kernel<true><<<node_blocks, 256, SM_TOTAL>>>(x, btf1, b1, h_ptr);

    // ----- Layer 2 -----
    agg_kernel<<<agg_blocks, 256>>>(h_ptr);
    node_kernel<false><<<node_blocks, 256, SM_TOTAL>>>(h_ptr, btf2, b2, out);
}

// round 11
// speedup vs baseline: 2.4441x; 1.3473x over previous
#include <cuda_runtime.h>
#include <cstdint>

#define NN 50000
#define DD 128
#define EMAX 800000

// Scratch (device globals: no allocation allowed)
__device__ float    g_mean[NN * DD];
__device__ float    g_h[NN * DD];
// Fragment-packed bf16 weights: [layer][h][s(16)][t(16)][lane(32)][q(2)] u32(bf16x2)
__device__ uint32_t g_bbf[2][2][16384];
__device__ int      g_deg[NN];
__device__ int      g_cur[NN];
__device__ int      g_rowptr[NN + 1];
__device__ int      g_esrc[EMAX];
__device__ int      g_idx64;

// ---------------------------------------------------------------------------
// bf16 split helper: (v0,v1) -> hi bf16x2 (lo half = v0), lo-residual bf16x2
// ---------------------------------------------------------------------------
__device__ __forceinline__ void bf16split2(float v0, float v1,
                                           uint32_t& hi, uint32_t& lo) {
    uint32_t h;
    asm("cvt.rn.bf16x2.f32 %0, %1, %2;" : "=r"(h) : "f"(v1), "f"(v0));
    float h0 = __uint_as_float(h << 16);
    float h1 = __uint_as_float(h & 0xffff0000u);
    float r0 = v0 - h0, r1 = v1 - h1;
    uint32_t l;
    asm("cvt.rn.bf16x2.f32 %0, %1, %2;" : "=r"(l) : "f"(r1), "f"(r0));
    hi = h; lo = l;
}

// ---------------------------------------------------------------------------
// Detect whether edge_index is int64 (hi words all zero) or int32.
// ---------------------------------------------------------------------------
__global__ void detect_kernel(const unsigned int* __restrict__ ei) {
    __shared__ int any_nonzero;
    if (threadIdx.x == 0) any_nonzero = 0;
    __syncthreads();
    if (ei[2 * threadIdx.x + 1] != 0u) atomicOr(&any_nonzero, 1);
    __syncthreads();
    if (threadIdx.x == 0) g_idx64 = (any_nonzero == 0) ? 1 : 0;
}

// ---------------------------------------------------------------------------
// Weight pack: bf16 hi/lo split in mma.m16n8k16 B-fragment order.
//   p = ((s*16 + t)*32 + l)*2 + q ;  k0 = 16s + 2(l&3) + 8q ; n = 8t + (l>>2)
//   u32 = bf16x2( Wcat^T[k0][n], Wcat^T[k0+1][n] )
// idx in [0, 32768): layer = idx>>14, p = idx & 16383.
// ---------------------------------------------------------------------------
__global__ void pack_kernel(const float* __restrict__ W1l,
                            const float* __restrict__ W1r,
                            const float* __restrict__ W2l,
                            const float* __restrict__ W2r) {
    int idx = blockIdx.x * blockDim.x + threadIdx.x;   // 0..32767
    int layer = idx >> 14;
    int p     = idx & 16383;
    int s = p >> 10;
    int t = (p >> 6) & 15;
    int l = (p >> 1) & 31;
    int q = p & 1;

    int k0 = 16 * s + 2 * (l & 3) + 8 * q;
    int n  = 8 * t + (l >> 2);

    const float* Wl = layer ? W2l : W1l;
    const float* Wr = layer ? W2r : W1r;
    float w0 = (k0 < 128) ? Wl[n * 128 + k0] : Wr[n * 128 + (k0 - 128)];
    float w1 = (k0 + 1 < 128) ? Wl[n * 128 + k0 + 1] : Wr[n * 128 + (k0 - 127)];

    uint32_t hi, lo;
    bf16split2(w0, w1, hi, lo);
    g_bbf[layer][0][p] = hi;
    g_bbf[layer][1][p] = lo;
}

// ---------------------------------------------------------------------------
// CSR build
// ---------------------------------------------------------------------------
__global__ void zero_small_kernel() {
    int i = blockIdx.x * blockDim.x + threadIdx.x;
    if (i < NN) { g_deg[i] = 0; g_cur[i] = 0; }
}

__device__ __forceinline__ int load_dst(const void* ei, unsigned e, unsigned E) {
    if (g_idx64) return (int)((const long long*)ei)[e + E];
    return ((const int*)ei)[e + E];
}
__device__ __forceinline__ int load_src(const void* ei, unsigned e, unsigned E) {
    if (g_idx64) return (int)((const long long*)ei)[e];
    return ((const int*)ei)[e];
}

__global__ void hist_kernel(const void* __restrict__ ei, int E) {
    unsigned e = blockIdx.x * blockDim.x + threadIdx.x;
    if (e >= (unsigned)E) return;
    atomicAdd(&g_deg[load_dst(ei, e, E)], 1);
}

__global__ void scan_kernel() {
    __shared__ int sp[1024];
    int t = threadIdx.x;
    const int CH = (NN + 1023) / 1024;  // 49
    int base = t * CH;
    int s = 0;
    for (int i = 0; i < CH; i++) {
        int idx = base + i;
        if (idx < NN) s += g_deg[idx];
    }
    sp[t] = s;
    __syncthreads();
    for (int off = 1; off < 1024; off <<= 1) {
        int v = (t >= off) ? sp[t - off] : 0;
        __syncthreads();
        sp[t] += v;
        __syncthreads();
    }
    int run = (t == 0) ? 0 : sp[t - 1];
    for (int i = 0; i < CH; i++) {
        int idx = base + i;
        if (idx < NN) { g_rowptr[idx] = run; run += g_deg[idx]; }
    }
    if (t == 1023) g_rowptr[NN] = run;
}

__global__ void scatter_kernel(const void* __restrict__ ei, int E) {
    unsigned e = blockIdx.x * blockDim.x + threadIdx.x;
    if (e >= (unsigned)E) return;
    int src = load_src(ei, e, E);
    int dst = load_dst(ei, e, E);
    int pos = g_rowptr[dst] + atomicAdd(&g_cur[dst], 1);
    g_esrc[pos] = src;
}

// ---------------------------------------------------------------------------
// Aggregation: one warp per destination node (mean fused, plain stores).
// ---------------------------------------------------------------------------
__global__ void __launch_bounds__(256)
agg_kernel(const float* __restrict__ xin) {
    int warp = (blockIdx.x * blockDim.x + threadIdx.x) >> 5;
    int lane = threadIdx.x & 31;
    if (warp >= NN) return;

    int start = g_rowptr[warp];
    int end   = g_rowptr[warp + 1];

    float4 acc = make_float4(0.f, 0.f, 0.f, 0.f);
    int j = start;
    for (; j + 4 <= end; j += 4) {
        int s0 = g_esrc[j + 0], s1 = g_esrc[j + 1];
        int s2 = g_esrc[j + 2], s3 = g_esrc[j + 3];
        float4 v0 = __ldg(((const float4*)(xin + (size_t)s0 * DD)) + lane);
        float4 v1 = __ldg(((const float4*)(xin + (size_t)s1 * DD)) + lane);
        float4 v2 = __ldg(((const float4*)(xin + (size_t)s2 * DD)) + lane);
        float4 v3 = __ldg(((const float4*)(xin + (size_t)s3 * DD)) + lane);
        acc.x += v0.x + v1.x + v2.x + v3.x;
        acc.y += v0.y + v1.y + v2.y + v3.y;
        acc.z += v0.z + v1.z + v2.z + v3.z;
        acc.w += v0.w + v1.w + v2.w + v3.w;
    }
    for (; j < end; j++) {
        int s = g_esrc[j];
        float4 v = __ldg(((const float4*)(xin + (size_t)s * DD)) + lane);
        acc.x += v.x; acc.y += v.y; acc.z += v.z; acc.w += v.w;
    }

    float inv = 1.0f / fmaxf((float)(end - start), 1.0f);
    acc.x *= inv; acc.y *= inv; acc.z *= inv; acc.w *= inv;
    ((float4*)(g_mean + (size_t)warp * DD))[lane] = acc;
}

// ---------------------------------------------------------------------------
// JAX threefry2x32-20, key=(0,42), partitionable. f64-uniform compare done
// exactly in integers: u < 0.8  <=>  (bits64>>12) < 3602879701896397.
// ---------------------------------------------------------------------------
__device__ __forceinline__ unsigned rotl32(unsigned x, int r) {
    return (x << r) | (x >> (32 - r));
}

__device__ __forceinline__ float drop_mask(unsigned f) {
    const unsigned k0 = 0u, k1 = 42u;
    const unsigned k2 = k0 ^ k1 ^ 0x1BD11BDAu;
    unsigned x0 = 0u + k0;
    unsigned x1 = f + k1;

#define TF_ROUND(r) do { x0 += x1; x1 = rotl32(x1, (r)); x1 ^= x0; } while (0)
#define TF_BLOCK_A  do { TF_ROUND(13); TF_ROUND(15); TF_ROUND(26); TF_ROUND(6);  } while (0)
#define TF_BLOCK_B  do { TF_ROUND(17); TF_ROUND(29); TF_ROUND(16); TF_ROUND(24); } while (0)

    TF_BLOCK_A; x0 += k1; x1 += k2 + 1u;
    TF_BLOCK_B; x0 += k2; x1 += k0 + 2u;
    TF_BLOCK_A; x0 += k0; x1 += k1 + 3u;
    TF_BLOCK_B; x0 += k1; x1 += k2 + 4u;
    TF_BLOCK_A; x0 += k2; x1 += k0 + 5u;

#undef TF_ROUND
#undef TF_BLOCK_A
#undef TF_BLOCK_B

    unsigned long long b =
        ((unsigned long long)x0 << 32) | (unsigned long long)x1;
    return ((b >> 12) < 3602879701896397ULL) ? 1.25f : 0.0f;
}

// ---------------------------------------------------------------------------
// Node update via mma.sync m16n8k16 bf16, 3-term hi/lo split:
//   out = [mean | x] @ Wcat^T + b ;  M=128/CTA, N=128, K=256 (2 chunks of 128)
// 8 warps = 4(M) x 2(N); warp tile 32x64 = 2 Mtiles x 8 Ntiles.
// A staged as packed bf16x2 hi/lo in smem (stride 68 words, conflict-free).
// ---------------------------------------------------------------------------
#define AS_STRIDE 68                              // u32 words per row
#define SM_BS     0                               // 16384 u32 = 65536 B
#define SM_AS     65536                           // 2*128*68 u32 = 69632 B
#define AS_LO_OFF 8704                            // u32 offset of lo plane
#define SM_BIAS   (65536 + 69632)
#define SM_TOTAL  (SM_BIAS + 512)

__device__ __forceinline__ void mma_bf16(float* c, const uint32_t* a,
                                         uint32_t b0, uint32_t b1) {
    asm volatile(
        "mma.sync.aligned.m16n8k16.row.col.f32.bf16.bf16.f32 "
        "{%0,%1,%2,%3}, {%4,%5,%6,%7}, {%8,%9}, {%0,%1,%2,%3};"
        : "+f"(c[0]), "+f"(c[1]), "+f"(c[2]), "+f"(c[3])
        : "r"(a[0]), "r"(a[1]), "r"(a[2]), "r"(a[3]), "r"(b0), "r"(b1));
}

template <bool DROP>
__global__ void __launch_bounds__(256, 1)
node_kernel(const float* __restrict__ xin,
            const uint32_t* __restrict__ btf,   // this layer's packed weights
            const float* __restrict__ bias,
            float* __restrict__ out) {
    extern __shared__ char smem[];
    uint32_t* Bs = (uint32_t*)(smem + SM_BS);
    uint32_t* As = (uint32_t*)(smem + SM_AS);
    float*    bs = (float*)(smem + SM_BIAS);

    int t    = threadIdx.x;
    int l    = t & 31;
    int warp = t >> 5;
    int mw   = warp >> 1;        // 0..3
    int nw   = warp & 1;         // 0..1
    int row0 = blockIdx.x * 128;

    if (t < 128) bs[t] = __ldg(bias + t);

    float acc[2][8][4];
#pragma unroll
    for (int i = 0; i < 2; i++)
#pragma unroll
        for (int tt = 0; tt < 8; tt++)
#pragma unroll
            for (int c = 0; c < 4; c++) acc[i][tt][c] = 0.f;

    for (int chunk = 0; chunk < 2; chunk++) {
        if (chunk) __syncthreads();

        // Stage A chunk: 128 rows x 128 cols -> bf16x2 hi/lo planes
        const float* src = chunk ? xin : g_mean;
        for (int i = t; i < 128 * 32; i += 256) {
            int r  = i >> 5, c4 = i & 31;
            int row = row0 + r;
            float4 v = make_float4(0.f, 0.f, 0.f, 0.f);
            if (row < NN)
                v = __ldg(((const float4*)(src + (size_t)row * DD)) + c4);
            uint32_t h0, l0, h1, l1;
            bf16split2(v.x, v.y, h0, l0);
            bf16split2(v.z, v.w, h1, l1);
            int base = r * AS_STRIDE + 2 * c4;
            As[base]     = h0;
            As[base + 1] = h1;
            As[AS_LO_OFF + base]     = l0;
            As[AS_LO_OFF + base + 1] = l1;
        }

        // Stage B chunk: hi (8192 u32) + lo (8192 u32)
        for (int i = t; i < 16384; i += 256) {
            int h = i >> 13;
            Bs[i] = __ldg(btf + h * 16384 + chunk * 8192 + (i & 8191));
        }
        __syncthreads();

        // Compute: 8 k-steps of k16
#pragma unroll
        for (int sp = 0; sp < 8; sp++) {
            uint32_t ah[2][4], al[2][4];
            int g = l >> 2, r = l & 3;
#pragma unroll
            for (int i = 0; i < 2; i++) {
                int rb = mw * 32 + i * 16;
                const uint32_t* A0 = As + (rb + g) * AS_STRIDE + 8 * sp + r;
                const uint32_t* A1 = As + (rb + g + 8) * AS_STRIDE + 8 * sp + r;
                ah[i][0] = A0[0];
                ah[i][1] = A1[0];
                ah[i][2] = A0[4];
                ah[i][3] = A1[4];
                al[i][0] = A0[AS_LO_OFF];
                al[i][1] = A1[AS_LO_OFF];
                al[i][2] = A0[AS_LO_OFF + 4];
                al[i][3] = A1[AS_LO_OFF + 4];
            }
#pragma unroll
            for (int tt = 0; tt < 8; tt++) {
                const uint32_t* Bp =
                    Bs + ((sp * 16) + (nw * 8 + tt)) * 64 + l * 2;
                uint32_t bh0 = Bp[0],    bh1 = Bp[1];
                uint32_t bl0 = Bp[8192], bl1 = Bp[8193];
#pragma unroll
                for (int i = 0; i < 2; i++) {
                    mma_bf16(acc[i][tt], ah[i], bh0, bh1);
                    mma_bf16(acc[i][tt], al[i], bh0, bh1);
                    mma_bf16(acc[i][tt], ah[i], bl0, bl1);
                }
            }
        }
    }

    // Epilogue: c0,c1 -> (row_a, col..col+1); c2,c3 -> (row_a+8, ...)
#pragma unroll
    for (int i = 0; i < 2; i++) {
#pragma unroll
        for (int tt = 0; tt < 8; tt++) {
            int row_a = row0 + mw * 32 + i * 16 + (l >> 2);
            int row_b = row_a + 8;
            int col   = nw * 64 + tt * 8 + 2 * (l & 3);
            float b0 = bs[col], b1 = bs[col + 1];

            if (row_a < NN) {
                float o0 = acc[i][tt][0] + b0;
                float o1 = acc[i][tt][1] + b1;
                if (DROP) {
                    unsigned f = (unsigned)row_a * DD + col;
                    o0 = fmaxf(o0, 0.f) * drop_mask(f);
                    o1 = fmaxf(o1, 0.f) * drop_mask(f + 1);
                }
                *(float2*)(out + (size_t)row_a * DD + col) = make_float2(o0, o1);
            }
            if (row_b < NN) {
                float o0 = acc[i][tt][2] + b0;
                float o1 = acc[i][tt][3] + b1;
                if (DROP) {
                    unsigned f = (unsigned)row_b * DD + col;
                    o0 = fmaxf(o0, 0.f) * drop_mask(f);
                    o1 = fmaxf(o1, 0.f) * drop_mask(f + 1);
                }
                *(float2*)(out + (size_t)row_b * DD + col) = make_float2(o0, o1);
            }
        }
    }
}

// ---------------------------------------------------------------------------
extern "C" void kernel_launch(void* const* d_in, const int* in_sizes, int n_in,
                              void* d_out, int out_size) {
    const float* x   = (const float*)d_in[0];
    const void*  ei  = d_in[1];
    const float* W1l = (const float*)d_in[2];
    const float* W1r = (const float*)d_in[3];
    const float* b1  = (const float*)d_in[4];
    const float* W2l = (const float*)d_in[5];
    const float* W2r = (const float*)d_in[6];
    const float* b2  = (const float*)d_in[7];
    float* out = (float*)d_out;

    int E = in_sizes[1] / 2;

    cudaFuncSetAttribute(node_kernel<true>,
                         cudaFuncAttributeMaxDynamicSharedMemorySize, SM_TOTAL);
    cudaFuncSetAttribute(node_kernel<false>,
                         cudaFuncAttributeMaxDynamicSharedMemorySize, SM_TOTAL);

    float* h_ptr = nullptr;
    uint32_t* btf_ptr = nullptr;
    cudaGetSymbolAddress((void**)&h_ptr, g_h);
    cudaGetSymbolAddress((void**)&btf_ptr, g_bbf);
    const uint32_t* btf1 = btf_ptr;
    const uint32_t* btf2 = btf_ptr + 2 * 16384;

    int edge_blocks = (E + 255) / 256;
    int agg_blocks  = (NN * 32 + 255) / 256;
    int node_blocks = (NN + 127) / 128;   // 391

    // ----- One-time per launch: CSR build + weight pack -----
    detect_kernel<<<1, 256>>>((const unsigned int*)ei);
    pack_kernel<<<128, 256>>>(W1l, W1r, W2l, W2r);
    zero_small_kernel<<<(NN + 255) / 256, 256>>>();
    hist_kernel<<<edge_blocks, 256>>>(ei, E);
    scan_kernel<<<1, 1024>>>();
    scatter_kernel<<<edge_blocks, 256>>>(ei, E);

    // ----- Layer 1 -----
    agg_kernel<<<agg_blocks, 256>>>(x);
    node_kernel<true><<<node_blocks, 256, SM_TOTAL>>>(x, btf1, b1, h_ptr);

    // ----- Layer 2 -----
    agg_kernel<<<agg_blocks, 256>>>(h_ptr);
    node_kernel<false><<<node_blocks, 256, SM_TOTAL>>>(h_ptr, btf2, b2, out);
}